// round 1
// baseline (speedup 1.0000x reference)
#include <cuda_runtime.h>
#include <cuda_bf16.h>

// Problem constants (fixed shapes for this dataset)
constexpr int MAXN = 50000;
constexpr int MAXE = 1250000;
constexpr int D    = 64;   // input / hidden1 width
constexpr int H2   = 16;
constexpr int OUTW = 2;

// ---------------- device scratch (no allocation allowed) ----------------
__device__ int   g_deg[MAXN];
__device__ int   g_fill[MAXN];
__device__ int   g_rowptr[MAXN + 1];
__device__ int   g_col[MAXE];            // src node per CSR-sorted (by dst) edge
__device__ float g_agg[(size_t)MAXN * D];
__device__ float g_h[(size_t)MAXN * D];

// ---------------- CSR build ----------------
__global__ void zero_kernel(int n) {
    int i = blockIdx.x * blockDim.x + threadIdx.x;
    if (i < n) { g_deg[i] = 0; g_fill[i] = 0; }
}

__global__ void hist_kernel(const int* __restrict__ dst, int E) {
    int i = blockIdx.x * blockDim.x + threadIdx.x;
    if (i < E) atomicAdd(&g_deg[dst[i]], 1);
}

// single-block exclusive scan over g_deg -> g_rowptr
__global__ void scan_kernel(int n, int E) {
    __shared__ int part[1024];
    int tid = threadIdx.x;
    int chunk = (n + 1023) / 1024;
    int base = tid * chunk;
    int sum = 0;
    for (int c = 0; c < chunk; c++) {
        int idx = base + c;
        if (idx < n) sum += g_deg[idx];
    }
    part[tid] = sum;
    __syncthreads();
    // Hillis-Steele inclusive scan
    for (int off = 1; off < 1024; off <<= 1) {
        int v = (tid >= off) ? part[tid - off] : 0;
        __syncthreads();
        part[tid] += v;
        __syncthreads();
    }
    int run = (tid == 0) ? 0 : part[tid - 1];
    for (int c = 0; c < chunk; c++) {
        int idx = base + c;
        if (idx < n) { g_rowptr[idx] = run; run += g_deg[idx]; }
    }
    if (tid == 0) g_rowptr[n] = E;
}

__global__ void fill_kernel(const int* __restrict__ src, const int* __restrict__ dst, int E) {
    int i = blockIdx.x * blockDim.x + threadIdx.x;
    if (i < E) {
        int d = dst[i];
        int p = atomicAdd(&g_fill[d], 1);
        g_col[g_rowptr[d] + p] = src[i];
    }
}

// ---------------- mean aggregation (gather over CSR) ----------------
// blockDim = (64, 4): 64 feature lanes, 4 nodes per block
__global__ void agg_kernel(const float* __restrict__ feat, float* __restrict__ out, int n) {
    int node = blockIdx.x * 4 + threadIdx.y;
    if (node >= n) return;
    int tx = threadIdx.x;
    int rs = g_rowptr[node];
    int re = g_rowptr[node + 1];
    float acc = 0.f;
    int p = rs;
    // unroll-by-2 for some MLP
    for (; p + 1 < re; p += 2) {
        int s0 = g_col[p];
        int s1 = g_col[p + 1];
        float v0 = feat[(size_t)s0 * D + tx];
        float v1 = feat[(size_t)s1 * D + tx];
        acc += v0 + v1;
    }
    if (p < re) {
        int s0 = g_col[p];
        acc += feat[(size_t)s0 * D + tx];
    }
    float cnt = (float)(re - rs);
    out[(size_t)node * D + tx] = acc / fmaxf(cnt, 1.f);
}

// ---------------- dense layer 1: h = relu(agg@W1l + x@W1r + b1) ----------------
// 256 threads: j = tid&31 (thread covers output j and j+32), warp-uniform node.
// 64 nodes per block.
__global__ void dense1_kernel(const float* __restrict__ agg, const float* __restrict__ x,
                              const float* __restrict__ W1l, const float* __restrict__ b1,
                              const float* __restrict__ W1r, float* __restrict__ h, int n) {
    __shared__ float sWl[D * D];
    __shared__ float sWr[D * D];
    __shared__ float sb[D];
    int tid = threadIdx.x;
    for (int i = tid; i < D * D; i += 256) { sWl[i] = W1l[i]; sWr[i] = W1r[i]; }
    if (tid < D) sb[tid] = b1[tid];
    __syncthreads();

    int j  = tid & 31;
    int il = tid >> 5;  // 0..7 (== warp id; node is warp-uniform)
    int base = blockIdx.x * 64;

    for (int s = 0; s < 64; s += 8) {
        int i = base + il + s;
        if (i >= n) break;
        const float4* a4 = reinterpret_cast<const float4*>(agg + (size_t)i * D);
        const float4* x4 = reinterpret_cast<const float4*>(x   + (size_t)i * D);
        float acc0 = sb[j];
        float acc1 = sb[j + 32];
#pragma unroll
        for (int k4 = 0; k4 < 16; k4++) {
            float4 a  = a4[k4];
            float4 xv = x4[k4];
            int k = k4 * 4;
            acc0 += a.x * sWl[(k + 0) * D + j] + xv.x * sWr[(k + 0) * D + j];
            acc0 += a.y * sWl[(k + 1) * D + j] + xv.y * sWr[(k + 1) * D + j];
            acc0 += a.z * sWl[(k + 2) * D + j] + xv.z * sWr[(k + 2) * D + j];
            acc0 += a.w * sWl[(k + 3) * D + j] + xv.w * sWr[(k + 3) * D + j];
            acc1 += a.x * sWl[(k + 0) * D + j + 32] + xv.x * sWr[(k + 0) * D + j + 32];
            acc1 += a.y * sWl[(k + 1) * D + j + 32] + xv.y * sWr[(k + 1) * D + j + 32];
            acc1 += a.z * sWl[(k + 2) * D + j + 32] + xv.z * sWr[(k + 2) * D + j + 32];
            acc1 += a.w * sWl[(k + 3) * D + j + 32] + xv.w * sWr[(k + 3) * D + j + 32];
        }
        h[(size_t)i * D + j]      = fmaxf(acc0, 0.f);
        h[(size_t)i * D + j + 32] = fmaxf(acc1, 0.f);
    }
}

// ---------------- dense layer 2 + fc fused ----------------
// h2 = agg2@W2l + h@W2r + b2 (16 wide), out = h2@Wfc + bfc (2 wide)
// 256 threads: j = tid&15 (output feature), il = tid>>4 (16 node lanes), 64 nodes/block
__global__ void dense2_kernel(const float* __restrict__ agg, const float* __restrict__ h,
                              const float* __restrict__ W2l, const float* __restrict__ b2,
                              const float* __restrict__ W2r, const float* __restrict__ Wfc,
                              const float* __restrict__ bfc, float* __restrict__ out, int n) {
    __shared__ float sWl[D * H2];
    __shared__ float sWr[D * H2];
    __shared__ float sb2[H2];
    __shared__ float sWfc[H2 * OUTW];
    __shared__ float sbfc[OUTW];
    int tid = threadIdx.x;
    for (int i = tid; i < D * H2; i += 256) { sWl[i] = W2l[i]; sWr[i] = W2r[i]; }
    if (tid < H2) sb2[tid] = b2[tid];
    if (tid < H2 * OUTW) sWfc[tid] = Wfc[tid];
    if (tid < OUTW) sbfc[tid] = bfc[tid];
    __syncthreads();

    int j  = tid & 15;
    int il = tid >> 4;  // 0..15
    int base = blockIdx.x * 64;

    for (int s = 0; s < 64; s += 16) {
        int i = base + il + s;
        bool valid = (i < n);
        int ic = valid ? i : (n - 1);
        const float4* a4 = reinterpret_cast<const float4*>(agg + (size_t)ic * D);
        const float4* h4 = reinterpret_cast<const float4*>(h   + (size_t)ic * D);
        float acc = sb2[j];
#pragma unroll
        for (int k4 = 0; k4 < 16; k4++) {
            float4 a  = a4[k4];
            float4 hv = h4[k4];
            int k = k4 * 4;
            acc += a.x * sWl[(k + 0) * H2 + j] + hv.x * sWr[(k + 0) * H2 + j];
            acc += a.y * sWl[(k + 1) * H2 + j] + hv.y * sWr[(k + 1) * H2 + j];
            acc += a.z * sWl[(k + 2) * H2 + j] + hv.z * sWr[(k + 2) * H2 + j];
            acc += a.w * sWl[(k + 3) * H2 + j] + hv.w * sWr[(k + 3) * H2 + j];
        }
        // fc: reduce across the 16 j-lanes
        float o0 = acc * sWfc[j * OUTW + 0];
        float o1 = acc * sWfc[j * OUTW + 1];
#pragma unroll
        for (int off = 8; off >= 1; off >>= 1) {
            o0 += __shfl_down_sync(0xffffffffu, o0, off, 16);
            o1 += __shfl_down_sync(0xffffffffu, o1, off, 16);
        }
        if (j == 0 && valid) {
            out[(size_t)i * OUTW + 0] = o0 + sbfc[0];
            out[(size_t)i * OUTW + 1] = o1 + sbfc[1];
        }
    }
}

// ---------------- launcher ----------------
extern "C" void kernel_launch(void* const* d_in, const int* in_sizes, int n_in,
                              void* d_out, int out_size) {
    const float* x   = (const float*)d_in[0];
    const int*   e   = (const int*)d_in[1];
    const float* W1l = (const float*)d_in[2];
    const float* b1  = (const float*)d_in[3];
    const float* W1r = (const float*)d_in[4];
    const float* W2l = (const float*)d_in[5];
    const float* b2  = (const float*)d_in[6];
    const float* W2r = (const float*)d_in[7];
    const float* Wfc = (const float*)d_in[8];
    const float* bfc = (const float*)d_in[9];
    float* out = (float*)d_out;

    int n = in_sizes[0] / D;
    int E = in_sizes[1] / 2;
    const int* src = e;
    const int* dst = e + E;

    // get device-global pointers for kernels that take feat args
    // (kernels reference globals directly; only feat/out pointers vary)
    float* aggp;
    float* hp;
    cudaGetSymbolAddress((void**)&aggp, g_agg);
    cudaGetSymbolAddress((void**)&hp, g_h);

    // 1) CSR build
    zero_kernel<<<(n + 255) / 256, 256>>>(n);
    hist_kernel<<<(E + 255) / 256, 256>>>(dst, E);
    scan_kernel<<<1, 1024>>>(n, E);
    fill_kernel<<<(E + 255) / 256, 256>>>(src, dst, E);

    // 2) layer 1
    dim3 aggBlk(64, 4);
    agg_kernel<<<(n + 3) / 4, aggBlk>>>(x, aggp, n);
    dense1_kernel<<<(n + 63) / 64, 256>>>(aggp, x, W1l, b1, W1r, hp, n);

    // 3) layer 2 + fc
    agg_kernel<<<(n + 3) / 4, aggBlk>>>(hp, aggp, n);
    dense2_kernel<<<(n + 63) / 64, 256>>>(aggp, hp, W2l, b2, W2r, Wfc, bfc, out, n);
}

// round 2
// speedup vs baseline: 1.2743x; 1.2743x over previous
#include <cuda_runtime.h>
#include <cuda_bf16.h>

constexpr int MAXN = 50000;
constexpr int MAXE = 1250000;
constexpr int D    = 64;
constexpr int H2   = 16;
constexpr int OUTW = 2;

// ---------------- device scratch ----------------
__device__ int   g_deg[MAXN];
__device__ int   g_start[MAXN];
__device__ int   g_fill[MAXN];
__device__ int   g_col[MAXE];
__device__ int   g_counter;
__device__ float g_agg[(size_t)MAXN * D];
__device__ float g_h[(size_t)MAXN * D];

// ---------------- CSR build ----------------
__global__ void zero_kernel(int n) {
    int i = blockIdx.x * blockDim.x + threadIdx.x;
    if (i < n) g_deg[i] = 0;
    if (i == 0) g_counter = 0;
}

__global__ void hist_kernel(const int* __restrict__ dst, int E) {
    int i = (blockIdx.x * blockDim.x + threadIdx.x) * 4;
    if (i + 3 < E) {
        int4 d = *reinterpret_cast<const int4*>(dst + i);
        atomicAdd(&g_deg[d.x], 1);
        atomicAdd(&g_deg[d.y], 1);
        atomicAdd(&g_deg[d.z], 1);
        atomicAdd(&g_deg[d.w], 1);
    } else {
        for (int k = i; k < E; k++) atomicAdd(&g_deg[dst[k]], 1);
    }
}

// bump-allocator: warp-scan degrees, one atomic per warp. Row segments are
// contiguous per node but not ordered by node id (aggregation doesn't care).
__global__ void alloc_kernel(int n) {
    int i = blockIdx.x * blockDim.x + threadIdx.x;
    int lane = threadIdx.x & 31;
    int deg = (i < n) ? g_deg[i] : 0;
    int incl = deg;
#pragma unroll
    for (int off = 1; off < 32; off <<= 1) {
        int v = __shfl_up_sync(0xffffffffu, incl, off);
        if (lane >= off) incl += v;
    }
    int excl = incl - deg;
    int base = 0;
    if (lane == 31) base = atomicAdd(&g_counter, incl);
    base = __shfl_sync(0xffffffffu, base, 31);
    if (i < n) {
        int s = base + excl;
        g_start[i] = s;
        g_fill[i]  = s;  // running write cursor for fill
    }
}

__global__ void fill_kernel(const int* __restrict__ src, const int* __restrict__ dst, int E) {
    int i = (blockIdx.x * blockDim.x + threadIdx.x) * 4;
    if (i + 3 < E) {
        int4 s = *reinterpret_cast<const int4*>(src + i);
        int4 d = *reinterpret_cast<const int4*>(dst + i);
        g_col[atomicAdd(&g_fill[d.x], 1)] = s.x;
        g_col[atomicAdd(&g_fill[d.y], 1)] = s.y;
        g_col[atomicAdd(&g_fill[d.z], 1)] = s.z;
        g_col[atomicAdd(&g_fill[d.w], 1)] = s.w;
    } else {
        for (int k = i; k < E; k++)
            g_col[atomicAdd(&g_fill[dst[k]], 1)] = src[k];
    }
}

// ---------------- mean aggregation (CSR gather, float4) ----------------
// 256 threads: each warp covers 2 nodes; 16 lanes x float4 = 64 features.
__global__ void agg_kernel(const float* __restrict__ feat, float* __restrict__ out, int n) {
    int warp = threadIdx.x >> 5;
    int lane = threadIdx.x & 31;
    int node = blockIdx.x * 16 + warp * 2 + (lane >> 4);
    if (node >= n) return;
    int sl = lane & 15;

    int rs  = g_start[node];
    int deg = g_deg[node];
    const float4* f4 = reinterpret_cast<const float4*>(feat);

    float4 acc = make_float4(0.f, 0.f, 0.f, 0.f);
#pragma unroll 4
    for (int p = 0; p < deg; p++) {
        int s = __ldg(&g_col[rs + p]);
        float4 v = __ldg(&f4[(size_t)s * 16 + sl]);
        acc.x += v.x; acc.y += v.y; acc.z += v.z; acc.w += v.w;
    }
    float inv = 1.f / fmaxf((float)deg, 1.f);
    acc.x *= inv; acc.y *= inv; acc.z *= inv; acc.w *= inv;
    reinterpret_cast<float4*>(out)[(size_t)node * 16 + sl] = acc;
}

// ---------------- dense layer 1: h = relu(agg@W1l + x@W1r + b1) ----------------
__global__ void dense1_kernel(const float* __restrict__ agg, const float* __restrict__ x,
                              const float* __restrict__ W1l, const float* __restrict__ b1,
                              const float* __restrict__ W1r, float* __restrict__ h, int n) {
    __shared__ float sWl[D * D];
    __shared__ float sWr[D * D];
    __shared__ float sb[D];
    int tid = threadIdx.x;
    for (int i = tid; i < D * D; i += 256) { sWl[i] = W1l[i]; sWr[i] = W1r[i]; }
    if (tid < D) sb[tid] = b1[tid];
    __syncthreads();

    int j  = tid & 31;
    int il = tid >> 5;
    int base = blockIdx.x * 64;

    for (int s = 0; s < 64; s += 8) {
        int i = base + il + s;
        if (i >= n) break;
        const float4* a4 = reinterpret_cast<const float4*>(agg + (size_t)i * D);
        const float4* x4 = reinterpret_cast<const float4*>(x   + (size_t)i * D);
        float acc0 = sb[j];
        float acc1 = sb[j + 32];
#pragma unroll
        for (int k4 = 0; k4 < 16; k4++) {
            float4 a  = a4[k4];
            float4 xv = x4[k4];
            int k = k4 * 4;
            acc0 += a.x * sWl[(k + 0) * D + j] + xv.x * sWr[(k + 0) * D + j];
            acc0 += a.y * sWl[(k + 1) * D + j] + xv.y * sWr[(k + 1) * D + j];
            acc0 += a.z * sWl[(k + 2) * D + j] + xv.z * sWr[(k + 2) * D + j];
            acc0 += a.w * sWl[(k + 3) * D + j] + xv.w * sWr[(k + 3) * D + j];
            acc1 += a.x * sWl[(k + 0) * D + j + 32] + xv.x * sWr[(k + 0) * D + j + 32];
            acc1 += a.y * sWl[(k + 1) * D + j + 32] + xv.y * sWr[(k + 1) * D + j + 32];
            acc1 += a.z * sWl[(k + 2) * D + j + 32] + xv.z * sWr[(k + 2) * D + j + 32];
            acc1 += a.w * sWl[(k + 3) * D + j + 32] + xv.w * sWr[(k + 3) * D + j + 32];
        }
        h[(size_t)i * D + j]      = fmaxf(acc0, 0.f);
        h[(size_t)i * D + j + 32] = fmaxf(acc1, 0.f);
    }
}

// ---------------- dense layer 2 + fc fused ----------------
__global__ void dense2_kernel(const float* __restrict__ agg, const float* __restrict__ h,
                              const float* __restrict__ W2l, const float* __restrict__ b2,
                              const float* __restrict__ W2r, const float* __restrict__ Wfc,
                              const float* __restrict__ bfc, float* __restrict__ out, int n) {
    __shared__ float sWl[D * H2];
    __shared__ float sWr[D * H2];
    __shared__ float sb2[H2];
    __shared__ float sWfc[H2 * OUTW];
    __shared__ float sbfc[OUTW];
    int tid = threadIdx.x;
    for (int i = tid; i < D * H2; i += 256) { sWl[i] = W2l[i]; sWr[i] = W2r[i]; }
    if (tid < H2) sb2[tid] = b2[tid];
    if (tid < H2 * OUTW) sWfc[tid] = Wfc[tid];
    if (tid < OUTW) sbfc[tid] = bfc[tid];
    __syncthreads();

    int j  = tid & 15;
    int il = tid >> 4;
    int base = blockIdx.x * 64;

    for (int s = 0; s < 64; s += 16) {
        int i = base + il + s;
        bool valid = (i < n);
        int ic = valid ? i : (n - 1);
        const float4* a4 = reinterpret_cast<const float4*>(agg + (size_t)ic * D);
        const float4* h4 = reinterpret_cast<const float4*>(h   + (size_t)ic * D);
        float acc = sb2[j];
#pragma unroll
        for (int k4 = 0; k4 < 16; k4++) {
            float4 a  = a4[k4];
            float4 hv = h4[k4];
            int k = k4 * 4;
            acc += a.x * sWl[(k + 0) * H2 + j] + hv.x * sWr[(k + 0) * H2 + j];
            acc += a.y * sWl[(k + 1) * H2 + j] + hv.y * sWr[(k + 1) * H2 + j];
            acc += a.z * sWl[(k + 2) * H2 + j] + hv.z * sWr[(k + 2) * H2 + j];
            acc += a.w * sWl[(k + 3) * H2 + j] + hv.w * sWr[(k + 3) * H2 + j];
        }
        float o0 = acc * sWfc[j * OUTW + 0];
        float o1 = acc * sWfc[j * OUTW + 1];
#pragma unroll
        for (int off = 8; off >= 1; off >>= 1) {
            o0 += __shfl_down_sync(0xffffffffu, o0, off, 16);
            o1 += __shfl_down_sync(0xffffffffu, o1, off, 16);
        }
        if (j == 0 && valid) {
            out[(size_t)i * OUTW + 0] = o0 + sbfc[0];
            out[(size_t)i * OUTW + 1] = o1 + sbfc[1];
        }
    }
}

// ---------------- launcher ----------------
extern "C" void kernel_launch(void* const* d_in, const int* in_sizes, int n_in,
                              void* d_out, int out_size) {
    const float* x   = (const float*)d_in[0];
    const int*   e   = (const int*)d_in[1];
    const float* W1l = (const float*)d_in[2];
    const float* b1  = (const float*)d_in[3];
    const float* W1r = (const float*)d_in[4];
    const float* W2l = (const float*)d_in[5];
    const float* b2  = (const float*)d_in[6];
    const float* W2r = (const float*)d_in[7];
    const float* Wfc = (const float*)d_in[8];
    const float* bfc = (const float*)d_in[9];
    float* out = (float*)d_out;

    int n = in_sizes[0] / D;
    int E = in_sizes[1] / 2;
    const int* src = e;
    const int* dst = e + E;

    float* aggp;
    float* hp;
    cudaGetSymbolAddress((void**)&aggp, g_agg);
    cudaGetSymbolAddress((void**)&hp, g_h);

    // 1) CSR build (no scan: warp-scan + bump allocator)
    zero_kernel<<<(n + 255) / 256, 256>>>(n);
    hist_kernel<<<(E / 4 + 255) / 256, 256>>>(dst, E);
    alloc_kernel<<<(n + 255) / 256, 256>>>(n);
    fill_kernel<<<(E / 4 + 255) / 256, 256>>>(src, dst, E);

    // 2) layer 1
    agg_kernel<<<(n + 15) / 16, 256>>>(x, aggp, n);
    dense1_kernel<<<(n + 63) / 64, 256>>>(aggp, x, W1l, b1, W1r, hp, n);

    // 3) layer 2 + fc
    agg_kernel<<<(n + 15) / 16, 256>>>(hp, aggp, n);
    dense2_kernel<<<(n + 63) / 64, 256>>>(aggp, hp, W2l, b2, W2r, Wfc, bfc, out, n);
}

// round 3
// speedup vs baseline: 1.5280x; 1.1991x over previous
#include <cuda_runtime.h>
#include <cuda_bf16.h>

constexpr int MAXN = 50000;
constexpr int MAXE = 1250000;
constexpr int D    = 64;
constexpr int H2   = 16;
constexpr int OUTW = 2;

// ---------------- device scratch ----------------
__device__ int   g_deg[MAXN];
__device__ int   g_start[MAXN];
__device__ int   g_fill[MAXN];
__device__ int   g_col[MAXE];
__device__ int   g_counter;
__device__ float g_agg[(size_t)MAXN * D];
__device__ float g_h[(size_t)MAXN * D];

// ---------------- CSR build ----------------
__global__ void zero_kernel(int n) {
    int i = blockIdx.x * blockDim.x + threadIdx.x;
    if (i < n) g_deg[i] = 0;
    if (i == 0) g_counter = 0;
}

__global__ void hist_kernel(const int* __restrict__ dst, int E) {
    int i = (blockIdx.x * blockDim.x + threadIdx.x) * 4;
    if (i + 3 < E) {
        int4 d = *reinterpret_cast<const int4*>(dst + i);
        atomicAdd(&g_deg[d.x], 1);
        atomicAdd(&g_deg[d.y], 1);
        atomicAdd(&g_deg[d.z], 1);
        atomicAdd(&g_deg[d.w], 1);
    } else {
        for (int k = i; k < E; k++) atomicAdd(&g_deg[dst[k]], 1);
    }
}

// bump-allocator: warp-scan degrees, one atomic per warp.
__global__ void alloc_kernel(int n) {
    int i = blockIdx.x * blockDim.x + threadIdx.x;
    int lane = threadIdx.x & 31;
    int deg = (i < n) ? g_deg[i] : 0;
    int incl = deg;
#pragma unroll
    for (int off = 1; off < 32; off <<= 1) {
        int v = __shfl_up_sync(0xffffffffu, incl, off);
        if (lane >= off) incl += v;
    }
    int excl = incl - deg;
    int base = 0;
    if (lane == 31) base = atomicAdd(&g_counter, incl);
    base = __shfl_sync(0xffffffffu, base, 31);
    if (i < n) {
        int s = base + excl;
        g_start[i] = s;
        g_fill[i]  = s;
    }
}

__global__ void fill_kernel(const int* __restrict__ src, const int* __restrict__ dst, int E) {
    int i = (blockIdx.x * blockDim.x + threadIdx.x) * 4;
    if (i + 3 < E) {
        int4 s = *reinterpret_cast<const int4*>(src + i);
        int4 d = *reinterpret_cast<const int4*>(dst + i);
        g_col[atomicAdd(&g_fill[d.x], 1)] = s.x;
        g_col[atomicAdd(&g_fill[d.y], 1)] = s.y;
        g_col[atomicAdd(&g_fill[d.z], 1)] = s.z;
        g_col[atomicAdd(&g_fill[d.w], 1)] = s.w;
    } else {
        for (int k = i; k < E; k++)
            g_col[atomicAdd(&g_fill[dst[k]], 1)] = src[k];
    }
}

// ---------------- mean aggregation: 1 warp per node, float2 lanes ----------------
__global__ void agg_kernel(const float* __restrict__ feat, float* __restrict__ out, int n) {
    int node = blockIdx.x * 8 + (threadIdx.x >> 5);
    if (node >= n) return;
    int lane = threadIdx.x & 31;

    int rs  = g_start[node];
    int deg = g_deg[node];
    const float2* f2 = reinterpret_cast<const float2*>(feat);
    const int* col = g_col + rs;

    float2 acc = make_float2(0.f, 0.f);
    int p = 0;
    for (; p + 4 <= deg; p += 4) {
        int s0 = __ldg(&col[p + 0]);
        int s1 = __ldg(&col[p + 1]);
        int s2 = __ldg(&col[p + 2]);
        int s3 = __ldg(&col[p + 3]);
        float2 v0 = __ldg(&f2[(size_t)s0 * 32 + lane]);
        float2 v1 = __ldg(&f2[(size_t)s1 * 32 + lane]);
        float2 v2 = __ldg(&f2[(size_t)s2 * 32 + lane]);
        float2 v3 = __ldg(&f2[(size_t)s3 * 32 + lane]);
        acc.x += (v0.x + v1.x) + (v2.x + v3.x);
        acc.y += (v0.y + v1.y) + (v2.y + v3.y);
    }
    for (; p < deg; p++) {
        int s = __ldg(&col[p]);
        float2 v = __ldg(&f2[(size_t)s * 32 + lane]);
        acc.x += v.x; acc.y += v.y;
    }
    float inv = 1.f / fmaxf((float)deg, 1.f);
    acc.x *= inv; acc.y *= inv;
    reinterpret_cast<float2*>(out)[(size_t)node * 32 + lane] = acc;
}

// ---------------- dense layer 1: h = relu(agg@W1l + x@W1r + b1) ----------------
// 256 threads = 8 warps. Each warp processes 4 nodes at a time (weight LDS
// amortized 4x). Block covers 64 nodes (2 quads per warp).
__global__ void dense1_kernel(const float* __restrict__ agg, const float* __restrict__ x,
                              const float* __restrict__ W1l, const float* __restrict__ b1,
                              const float* __restrict__ W1r, float* __restrict__ h, int n) {
    __shared__ float sWl[D * D];
    __shared__ float sWr[D * D];
    __shared__ float sb[D];
    int tid = threadIdx.x;
    for (int i = tid; i < D * D; i += 256) { sWl[i] = W1l[i]; sWr[i] = W1r[i]; }
    if (tid < D) sb[tid] = b1[tid];
    __syncthreads();

    int j = tid & 31;
    int w = tid >> 5;

    for (int s = 0; s < 2; s++) {
        int i0 = blockIdx.x * 64 + w * 4 + s * 32;
        if (i0 >= n) break;
        int i1 = min(i0 + 1, n - 1);
        int i2 = min(i0 + 2, n - 1);
        int i3 = min(i0 + 3, n - 1);

        const float4* aA = reinterpret_cast<const float4*>(agg + (size_t)i0 * D);
        const float4* aB = reinterpret_cast<const float4*>(agg + (size_t)i1 * D);
        const float4* aC = reinterpret_cast<const float4*>(agg + (size_t)i2 * D);
        const float4* aD = reinterpret_cast<const float4*>(agg + (size_t)i3 * D);
        const float4* xA = reinterpret_cast<const float4*>(x + (size_t)i0 * D);
        const float4* xB = reinterpret_cast<const float4*>(x + (size_t)i1 * D);
        const float4* xC = reinterpret_cast<const float4*>(x + (size_t)i2 * D);
        const float4* xD = reinterpret_cast<const float4*>(x + (size_t)i3 * D);

        float accA0 = sb[j], accA1 = sb[j + 32];
        float accB0 = sb[j], accB1 = sb[j + 32];
        float accC0 = sb[j], accC1 = sb[j + 32];
        float accD0 = sb[j], accD1 = sb[j + 32];

#pragma unroll
        for (int k4 = 0; k4 < 16; k4++) {
            float4 fa0 = aA[k4], fa1 = aB[k4], fa2 = aC[k4], fa3 = aD[k4];
            float4 fx0 = xA[k4], fx1 = xB[k4], fx2 = xC[k4], fx3 = xD[k4];
            int k = k4 * 4;
#pragma unroll
            for (int c = 0; c < 4; c++) {
                float wl0 = sWl[(k + c) * D + j];
                float wl1 = sWl[(k + c) * D + j + 32];
                float wr0 = sWr[(k + c) * D + j];
                float wr1 = sWr[(k + c) * D + j + 32];
                float a0 = (&fa0.x)[c], a1 = (&fa1.x)[c], a2 = (&fa2.x)[c], a3 = (&fa3.x)[c];
                float v0 = (&fx0.x)[c], v1 = (&fx1.x)[c], v2 = (&fx2.x)[c], v3 = (&fx3.x)[c];
                accA0 += a0 * wl0 + v0 * wr0;  accA1 += a0 * wl1 + v0 * wr1;
                accB0 += a1 * wl0 + v1 * wr0;  accB1 += a1 * wl1 + v1 * wr1;
                accC0 += a2 * wl0 + v2 * wr0;  accC1 += a2 * wl1 + v2 * wr1;
                accD0 += a3 * wl0 + v3 * wr0;  accD1 += a3 * wl1 + v3 * wr1;
            }
        }
        h[(size_t)i0 * D + j]      = fmaxf(accA0, 0.f);
        h[(size_t)i0 * D + j + 32] = fmaxf(accA1, 0.f);
        if (i0 + 1 < n) { h[(size_t)i1 * D + j] = fmaxf(accB0, 0.f); h[(size_t)i1 * D + j + 32] = fmaxf(accB1, 0.f); }
        if (i0 + 2 < n) { h[(size_t)i2 * D + j] = fmaxf(accC0, 0.f); h[(size_t)i2 * D + j + 32] = fmaxf(accC1, 0.f); }
        if (i0 + 3 < n) { h[(size_t)i3 * D + j] = fmaxf(accD0, 0.f); h[(size_t)i3 * D + j + 32] = fmaxf(accD1, 0.f); }
    }
}

// ---------------- dense layer 2 + fc fused ----------------
__global__ void dense2_kernel(const float* __restrict__ agg, const float* __restrict__ h,
                              const float* __restrict__ W2l, const float* __restrict__ b2,
                              const float* __restrict__ W2r, const float* __restrict__ Wfc,
                              const float* __restrict__ bfc, float* __restrict__ out, int n) {
    __shared__ float sWl[D * H2];
    __shared__ float sWr[D * H2];
    __shared__ float sb2[H2];
    __shared__ float sWfc[H2 * OUTW];
    __shared__ float sbfc[OUTW];
    int tid = threadIdx.x;
    for (int i = tid; i < D * H2; i += 256) { sWl[i] = W2l[i]; sWr[i] = W2r[i]; }
    if (tid < H2) sb2[tid] = b2[tid];
    if (tid < H2 * OUTW) sWfc[tid] = Wfc[tid];
    if (tid < OUTW) sbfc[tid] = bfc[tid];
    __syncthreads();

    int j  = tid & 15;
    int il = tid >> 4;
    int base = blockIdx.x * 64;

    for (int s = 0; s < 64; s += 16) {
        int i = base + il + s;
        bool valid = (i < n);
        int ic = valid ? i : (n - 1);
        const float4* a4 = reinterpret_cast<const float4*>(agg + (size_t)ic * D);
        const float4* h4 = reinterpret_cast<const float4*>(h   + (size_t)ic * D);
        float acc = sb2[j];
#pragma unroll
        for (int k4 = 0; k4 < 16; k4++) {
            float4 a  = a4[k4];
            float4 hv = h4[k4];
            int k = k4 * 4;
            acc += a.x * sWl[(k + 0) * H2 + j] + hv.x * sWr[(k + 0) * H2 + j];
            acc += a.y * sWl[(k + 1) * H2 + j] + hv.y * sWr[(k + 1) * H2 + j];
            acc += a.z * sWl[(k + 2) * H2 + j] + hv.z * sWr[(k + 2) * H2 + j];
            acc += a.w * sWl[(k + 3) * H2 + j] + hv.w * sWr[(k + 3) * H2 + j];
        }
        float o0 = acc * sWfc[j * OUTW + 0];
        float o1 = acc * sWfc[j * OUTW + 1];
#pragma unroll
        for (int off = 8; off >= 1; off >>= 1) {
            o0 += __shfl_down_sync(0xffffffffu, o0, off, 16);
            o1 += __shfl_down_sync(0xffffffffu, o1, off, 16);
        }
        if (j == 0 && valid) {
            out[(size_t)i * OUTW + 0] = o0 + sbfc[0];
            out[(size_t)i * OUTW + 1] = o1 + sbfc[1];
        }
    }
}

// ---------------- launcher ----------------
extern "C" void kernel_launch(void* const* d_in, const int* in_sizes, int n_in,
                              void* d_out, int out_size) {
    const float* x   = (const float*)d_in[0];
    const int*   e   = (const int*)d_in[1];
    const float* W1l = (const float*)d_in[2];
    const float* b1  = (const float*)d_in[3];
    const float* W1r = (const float*)d_in[4];
    const float* W2l = (const float*)d_in[5];
    const float* b2  = (const float*)d_in[6];
    const float* W2r = (const float*)d_in[7];
    const float* Wfc = (const float*)d_in[8];
    const float* bfc = (const float*)d_in[9];
    float* out = (float*)d_out;

    int n = in_sizes[0] / D;
    int E = in_sizes[1] / 2;
    const int* src = e;
    const int* dst = e + E;

    float* aggp;
    float* hp;
    cudaGetSymbolAddress((void**)&aggp, g_agg);
    cudaGetSymbolAddress((void**)&hp, g_h);

    // 1) CSR build
    zero_kernel<<<(n + 255) / 256, 256>>>(n);
    hist_kernel<<<(E / 4 + 255) / 256, 256>>>(dst, E);
    alloc_kernel<<<(n + 255) / 256, 256>>>(n);
    fill_kernel<<<(E / 4 + 255) / 256, 256>>>(src, dst, E);

    // 2) layer 1
    agg_kernel<<<(n + 7) / 8, 256>>>(x, aggp, n);
    dense1_kernel<<<(n + 63) / 64, 256>>>(aggp, x, W1l, b1, W1r, hp, n);

    // 3) layer 2 + fc
    agg_kernel<<<(n + 7) / 8, 256>>>(hp, aggp, n);
    dense2_kernel<<<(n + 63) / 64, 256>>>(aggp, hp, W2l, b2, W2r, Wfc, bfc, out, n);
}

// round 4
// speedup vs baseline: 1.7354x; 1.1357x over previous
#include <cuda_runtime.h>
#include <cuda_bf16.h>

constexpr int MAXN = 50000;
constexpr int MAXE = 1250000;
constexpr int D    = 64;
constexpr int H2   = 16;
constexpr int OUTW = 2;

// ---------------- device scratch ----------------
__device__ int   g_deg[MAXN];
__device__ int   g_start[MAXN];
__device__ int   g_fill[MAXN];
__device__ int   g_col[MAXE];
__device__ int   g_counter;
__device__ float g_agg[(size_t)MAXN * D];   // layer-1 aggregated features
__device__ float g_h[(size_t)MAXN * D];    // layer-1 output
__device__ float g_hl[(size_t)MAXN * H2];  // h @ W2l (pre-aggregation transform)
__device__ float g_agg2[(size_t)MAXN * H2]; // aggregated hl

// ---------------- CSR build ----------------
__global__ void zero_kernel(int n) {
    int i = blockIdx.x * blockDim.x + threadIdx.x;
    if (i < n) g_deg[i] = 0;
    if (i == 0) g_counter = 0;
}

__global__ void hist_kernel(const int* __restrict__ dst, int E) {
    int i = (blockIdx.x * blockDim.x + threadIdx.x) * 8;
    if (i + 7 < E) {
        int4 d0 = *reinterpret_cast<const int4*>(dst + i);
        int4 d1 = *reinterpret_cast<const int4*>(dst + i + 4);
        atomicAdd(&g_deg[d0.x], 1); atomicAdd(&g_deg[d0.y], 1);
        atomicAdd(&g_deg[d0.z], 1); atomicAdd(&g_deg[d0.w], 1);
        atomicAdd(&g_deg[d1.x], 1); atomicAdd(&g_deg[d1.y], 1);
        atomicAdd(&g_deg[d1.z], 1); atomicAdd(&g_deg[d1.w], 1);
    } else {
        for (int k = i; k < E; k++) atomicAdd(&g_deg[dst[k]], 1);
    }
}

__global__ void alloc_kernel(int n) {
    int i = blockIdx.x * blockDim.x + threadIdx.x;
    int lane = threadIdx.x & 31;
    int deg = (i < n) ? g_deg[i] : 0;
    int incl = deg;
#pragma unroll
    for (int off = 1; off < 32; off <<= 1) {
        int v = __shfl_up_sync(0xffffffffu, incl, off);
        if (lane >= off) incl += v;
    }
    int excl = incl - deg;
    int base = 0;
    if (lane == 31) base = atomicAdd(&g_counter, incl);
    base = __shfl_sync(0xffffffffu, base, 31);
    if (i < n) {
        int s = base + excl;
        g_start[i] = s;
        g_fill[i]  = s;
    }
}

__global__ void fill_kernel(const int* __restrict__ src, const int* __restrict__ dst, int E) {
    int i = (blockIdx.x * blockDim.x + threadIdx.x) * 8;
    if (i + 7 < E) {
        int4 s0 = *reinterpret_cast<const int4*>(src + i);
        int4 s1 = *reinterpret_cast<const int4*>(src + i + 4);
        int4 d0 = *reinterpret_cast<const int4*>(dst + i);
        int4 d1 = *reinterpret_cast<const int4*>(dst + i + 4);
        g_col[atomicAdd(&g_fill[d0.x], 1)] = s0.x;
        g_col[atomicAdd(&g_fill[d0.y], 1)] = s0.y;
        g_col[atomicAdd(&g_fill[d0.z], 1)] = s0.z;
        g_col[atomicAdd(&g_fill[d0.w], 1)] = s0.w;
        g_col[atomicAdd(&g_fill[d1.x], 1)] = s1.x;
        g_col[atomicAdd(&g_fill[d1.y], 1)] = s1.y;
        g_col[atomicAdd(&g_fill[d1.z], 1)] = s1.z;
        g_col[atomicAdd(&g_fill[d1.w], 1)] = s1.w;
    } else {
        for (int k = i; k < E; k++)
            g_col[atomicAdd(&g_fill[dst[k]], 1)] = src[k];
    }
}

// ---------------- agg64: mean over neighbors, 64-wide rows ----------------
// One warp per node; 32 col indices prefetched coalesced + shfl broadcast.
__global__ void agg64_kernel(const float* __restrict__ feat, float* __restrict__ out, int n) {
    int node = blockIdx.x * 8 + (threadIdx.x >> 5);
    if (node >= n) return;
    int lane = threadIdx.x & 31;

    int rs  = g_start[node];
    int deg = g_deg[node];
    const float2* f2 = reinterpret_cast<const float2*>(feat);

    float2 acc = make_float2(0.f, 0.f);
    for (int base = 0; base < deg; base += 32) {
        int m = min(32, deg - base);
        int c = (lane < m) ? __ldg(&g_col[rs + base + lane]) : 0;
        int q = 0;
        for (; q + 4 <= m; q += 4) {
            int s0 = __shfl_sync(0xffffffffu, c, q + 0);
            int s1 = __shfl_sync(0xffffffffu, c, q + 1);
            int s2 = __shfl_sync(0xffffffffu, c, q + 2);
            int s3 = __shfl_sync(0xffffffffu, c, q + 3);
            float2 v0 = __ldg(&f2[(size_t)s0 * 32 + lane]);
            float2 v1 = __ldg(&f2[(size_t)s1 * 32 + lane]);
            float2 v2 = __ldg(&f2[(size_t)s2 * 32 + lane]);
            float2 v3 = __ldg(&f2[(size_t)s3 * 32 + lane]);
            acc.x += (v0.x + v1.x) + (v2.x + v3.x);
            acc.y += (v0.y + v1.y) + (v2.y + v3.y);
        }
        for (; q < m; q++) {
            int s = __shfl_sync(0xffffffffu, c, q);
            float2 v = __ldg(&f2[(size_t)s * 32 + lane]);
            acc.x += v.x; acc.y += v.y;
        }
    }
    float inv = 1.f / fmaxf((float)deg, 1.f);
    acc.x *= inv; acc.y *= inv;
    reinterpret_cast<float2*>(out)[(size_t)node * 32 + lane] = acc;
}

// ---------------- agg16: mean over neighbors, 16-wide rows ----------------
// Half-warp per node (16 lanes x float); 16 cols prefetched + width-16 shfl.
__global__ void agg16_kernel(const float* __restrict__ feat, float* __restrict__ out, int n) {
    int node = blockIdx.x * 16 + (threadIdx.x >> 4);
    if (node >= n) return;
    int hlane = threadIdx.x & 15;

    int rs  = g_start[node];
    int deg = g_deg[node];

    float acc = 0.f;
    for (int base = 0; base < deg; base += 16) {
        int m = min(16, deg - base);
        int c = (hlane < m) ? __ldg(&g_col[rs + base + hlane]) : 0;
        int q = 0;
        for (; q + 4 <= m; q += 4) {
            int s0 = __shfl_sync(0xffffffffu, c, q + 0, 16);
            int s1 = __shfl_sync(0xffffffffu, c, q + 1, 16);
            int s2 = __shfl_sync(0xffffffffu, c, q + 2, 16);
            int s3 = __shfl_sync(0xffffffffu, c, q + 3, 16);
            float v0 = __ldg(&feat[(size_t)s0 * H2 + hlane]);
            float v1 = __ldg(&feat[(size_t)s1 * H2 + hlane]);
            float v2 = __ldg(&feat[(size_t)s2 * H2 + hlane]);
            float v3 = __ldg(&feat[(size_t)s3 * H2 + hlane]);
            acc += (v0 + v1) + (v2 + v3);
        }
        for (; q < m; q++) {
            int s = __shfl_sync(0xffffffffu, c, q, 16);
            acc += __ldg(&feat[(size_t)s * H2 + hlane]);
        }
    }
    out[(size_t)node * H2 + hlane] = acc / fmaxf((float)deg, 1.f);
}

// ---------------- dense layer 1: h = relu(agg@W1l + x@W1r + b1) ----------------
__global__ void dense1_kernel(const float* __restrict__ agg, const float* __restrict__ x,
                              const float* __restrict__ W1l, const float* __restrict__ b1,
                              const float* __restrict__ W1r, float* __restrict__ h, int n) {
    __shared__ float sWl[D * D];
    __shared__ float sWr[D * D];
    __shared__ float sb[D];
    int tid = threadIdx.x;
    for (int i = tid; i < D * D; i += 256) { sWl[i] = W1l[i]; sWr[i] = W1r[i]; }
    if (tid < D) sb[tid] = b1[tid];
    __syncthreads();

    int j = tid & 31;
    int w = tid >> 5;

    for (int s = 0; s < 2; s++) {
        int i0 = blockIdx.x * 64 + w * 4 + s * 32;
        if (i0 >= n) break;
        int i1 = min(i0 + 1, n - 1);
        int i2 = min(i0 + 2, n - 1);
        int i3 = min(i0 + 3, n - 1);

        const float4* aA = reinterpret_cast<const float4*>(agg + (size_t)i0 * D);
        const float4* aB = reinterpret_cast<const float4*>(agg + (size_t)i1 * D);
        const float4* aC = reinterpret_cast<const float4*>(agg + (size_t)i2 * D);
        const float4* aD = reinterpret_cast<const float4*>(agg + (size_t)i3 * D);
        const float4* xA = reinterpret_cast<const float4*>(x + (size_t)i0 * D);
        const float4* xB = reinterpret_cast<const float4*>(x + (size_t)i1 * D);
        const float4* xC = reinterpret_cast<const float4*>(x + (size_t)i2 * D);
        const float4* xD = reinterpret_cast<const float4*>(x + (size_t)i3 * D);

        float accA0 = sb[j], accA1 = sb[j + 32];
        float accB0 = sb[j], accB1 = sb[j + 32];
        float accC0 = sb[j], accC1 = sb[j + 32];
        float accD0 = sb[j], accD1 = sb[j + 32];

#pragma unroll
        for (int k4 = 0; k4 < 16; k4++) {
            float4 fa0 = aA[k4], fa1 = aB[k4], fa2 = aC[k4], fa3 = aD[k4];
            float4 fx0 = xA[k4], fx1 = xB[k4], fx2 = xC[k4], fx3 = xD[k4];
            int k = k4 * 4;
#pragma unroll
            for (int c = 0; c < 4; c++) {
                float wl0 = sWl[(k + c) * D + j];
                float wl1 = sWl[(k + c) * D + j + 32];
                float wr0 = sWr[(k + c) * D + j];
                float wr1 = sWr[(k + c) * D + j + 32];
                float a0 = (&fa0.x)[c], a1 = (&fa1.x)[c], a2 = (&fa2.x)[c], a3 = (&fa3.x)[c];
                float v0 = (&fx0.x)[c], v1 = (&fx1.x)[c], v2 = (&fx2.x)[c], v3 = (&fx3.x)[c];
                accA0 += a0 * wl0 + v0 * wr0;  accA1 += a0 * wl1 + v0 * wr1;
                accB0 += a1 * wl0 + v1 * wr0;  accB1 += a1 * wl1 + v1 * wr1;
                accC0 += a2 * wl0 + v2 * wr0;  accC1 += a2 * wl1 + v2 * wr1;
                accD0 += a3 * wl0 + v3 * wr0;  accD1 += a3 * wl1 + v3 * wr1;
            }
        }
        h[(size_t)i0 * D + j]      = fmaxf(accA0, 0.f);
        h[(size_t)i0 * D + j + 32] = fmaxf(accA1, 0.f);
        if (i0 + 1 < n) { h[(size_t)i1 * D + j] = fmaxf(accB0, 0.f); h[(size_t)i1 * D + j + 32] = fmaxf(accB1, 0.f); }
        if (i0 + 2 < n) { h[(size_t)i2 * D + j] = fmaxf(accC0, 0.f); h[(size_t)i2 * D + j + 32] = fmaxf(accC1, 0.f); }
        if (i0 + 3 < n) { h[(size_t)i3 * D + j] = fmaxf(accD0, 0.f); h[(size_t)i3 * D + j + 32] = fmaxf(accD1, 0.f); }
    }
}

// ---------------- dense1b: hl = h @ W2l (N x 16) ----------------
__global__ void dense1b_kernel(const float* __restrict__ h, const float* __restrict__ W2l,
                               float* __restrict__ hl, int n) {
    __shared__ float sW[D * H2];
    int tid = threadIdx.x;
    for (int i = tid; i < D * H2; i += 256) sW[i] = W2l[i];
    __syncthreads();

    int j  = tid & 15;
    int il = tid >> 4;
    int base = blockIdx.x * 64;

    for (int s = 0; s < 64; s += 16) {
        int i = base + il + s;
        if (i >= n) continue;
        const float4* h4 = reinterpret_cast<const float4*>(h + (size_t)i * D);
        float acc = 0.f;
#pragma unroll
        for (int k4 = 0; k4 < 16; k4++) {
            float4 hv = h4[k4];
            int k = k4 * 4;
            acc += hv.x * sW[(k + 0) * H2 + j];
            acc += hv.y * sW[(k + 1) * H2 + j];
            acc += hv.z * sW[(k + 2) * H2 + j];
            acc += hv.w * sW[(k + 3) * H2 + j];
        }
        hl[(size_t)i * H2 + j] = acc;
    }
}

// ---------------- dense2 + fc: out = (agg2 + h@W2r + b2) @ Wfc + bfc ----------------
__global__ void dense2_kernel(const float* __restrict__ agg2, const float* __restrict__ h,
                              const float* __restrict__ W2r, const float* __restrict__ b2,
                              const float* __restrict__ Wfc, const float* __restrict__ bfc,
                              float* __restrict__ out, int n) {
    __shared__ float sWr[D * H2];
    __shared__ float sb2[H2];
    __shared__ float sWfc[H2 * OUTW];
    __shared__ float sbfc[OUTW];
    int tid = threadIdx.x;
    for (int i = tid; i < D * H2; i += 256) sWr[i] = W2r[i];
    if (tid < H2) sb2[tid] = b2[tid];
    if (tid < H2 * OUTW) sWfc[tid] = Wfc[tid];
    if (tid < OUTW) sbfc[tid] = bfc[tid];
    __syncthreads();

    int j  = tid & 15;
    int il = tid >> 4;
    int base = blockIdx.x * 64;

    for (int s = 0; s < 64; s += 16) {
        int i = base + il + s;
        bool valid = (i < n);
        int ic = valid ? i : (n - 1);
        const float4* h4 = reinterpret_cast<const float4*>(h + (size_t)ic * D);
        float acc = sb2[j] + agg2[(size_t)ic * H2 + j];
#pragma unroll
        for (int k4 = 0; k4 < 16; k4++) {
            float4 hv = h4[k4];
            int k = k4 * 4;
            acc += hv.x * sWr[(k + 0) * H2 + j];
            acc += hv.y * sWr[(k + 1) * H2 + j];
            acc += hv.z * sWr[(k + 2) * H2 + j];
            acc += hv.w * sWr[(k + 3) * H2 + j];
        }
        float o0 = acc * sWfc[j * OUTW + 0];
        float o1 = acc * sWfc[j * OUTW + 1];
#pragma unroll
        for (int off = 8; off >= 1; off >>= 1) {
            o0 += __shfl_down_sync(0xffffffffu, o0, off, 16);
            o1 += __shfl_down_sync(0xffffffffu, o1, off, 16);
        }
        if (j == 0 && valid) {
            out[(size_t)i * OUTW + 0] = o0 + sbfc[0];
            out[(size_t)i * OUTW + 1] = o1 + sbfc[1];
        }
    }
}

// ---------------- launcher ----------------
extern "C" void kernel_launch(void* const* d_in, const int* in_sizes, int n_in,
                              void* d_out, int out_size) {
    const float* x   = (const float*)d_in[0];
    const int*   e   = (const int*)d_in[1];
    const float* W1l = (const float*)d_in[2];
    const float* b1  = (const float*)d_in[3];
    const float* W1r = (const float*)d_in[4];
    const float* W2l = (const float*)d_in[5];
    const float* b2  = (const float*)d_in[6];
    const float* W2r = (const float*)d_in[7];
    const float* Wfc = (const float*)d_in[8];
    const float* bfc = (const float*)d_in[9];
    float* out = (float*)d_out;

    int n = in_sizes[0] / D;
    int E = in_sizes[1] / 2;
    const int* src = e;
    const int* dst = e + E;

    float *aggp, *hp, *hlp, *agg2p;
    cudaGetSymbolAddress((void**)&aggp, g_agg);
    cudaGetSymbolAddress((void**)&hp, g_h);
    cudaGetSymbolAddress((void**)&hlp, g_hl);
    cudaGetSymbolAddress((void**)&agg2p, g_agg2);

    // 1) CSR build
    zero_kernel<<<(n + 255) / 256, 256>>>(n);
    hist_kernel<<<(E / 8 + 255) / 256, 256>>>(dst, E);
    alloc_kernel<<<(n + 255) / 256, 256>>>(n);
    fill_kernel<<<(E / 8 + 255) / 256, 256>>>(src, dst, E);

    // 2) layer 1
    agg64_kernel<<<(n + 7) / 8, 256>>>(x, aggp, n);
    dense1_kernel<<<(n + 63) / 64, 256>>>(aggp, x, W1l, b1, W1r, hp, n);

    // 3) layer 2: transform-then-aggregate (linearity of mean)
    dense1b_kernel<<<(n + 63) / 64, 256>>>(hp, W2l, hlp, n);
    agg16_kernel<<<(n + 15) / 16, 256>>>(hlp, agg2p, n);
    dense2_kernel<<<(n + 63) / 64, 256>>>(agg2p, hp, W2r, b2, Wfc, bfc, out, n);
}

// round 7
// speedup vs baseline: 1.8279x; 1.0533x over previous
#include <cuda_runtime.h>
#include <cuda_bf16.h>

constexpr int MAXN = 50000;
constexpr int MAXE = 1250000;
constexpr int D    = 64;
constexpr int H2   = 16;
constexpr int OUTW = 2;

// ---------------- device scratch ----------------
__device__ int   g_deg[MAXN];
__device__ int   g_start[MAXN];
__device__ int   g_fill[MAXN];
__device__ int   g_col[MAXE];
__device__ int   g_counter;
__device__ float g_xl[(size_t)MAXN * D];    // x @ W1l
__device__ float g_xr[(size_t)MAXN * D];    // x @ W1r + b1
__device__ float g_h[(size_t)MAXN * D];     // layer-1 output
__device__ float g_hl[(size_t)MAXN * H2];   // h @ W2l
__device__ float g_agg2[(size_t)MAXN * H2]; // aggregated hl

// ---------------- CSR build (verbatim from R4/passing) ----------------
__global__ void zero_kernel(int n) {
    int i = blockIdx.x * blockDim.x + threadIdx.x;
    if (i < n) g_deg[i] = 0;
    if (i == 0) g_counter = 0;
}

__global__ void hist_kernel(const int* __restrict__ dst, int E) {
    int i = (blockIdx.x * blockDim.x + threadIdx.x) * 8;
    if (i + 7 < E) {
        int4 d0 = *reinterpret_cast<const int4*>(dst + i);
        int4 d1 = *reinterpret_cast<const int4*>(dst + i + 4);
        atomicAdd(&g_deg[d0.x], 1); atomicAdd(&g_deg[d0.y], 1);
        atomicAdd(&g_deg[d0.z], 1); atomicAdd(&g_deg[d0.w], 1);
        atomicAdd(&g_deg[d1.x], 1); atomicAdd(&g_deg[d1.y], 1);
        atomicAdd(&g_deg[d1.z], 1); atomicAdd(&g_deg[d1.w], 1);
    } else {
        for (int k = i; k < E; k++) atomicAdd(&g_deg[dst[k]], 1);
    }
}

__global__ void alloc_kernel(int n) {
    int i = blockIdx.x * blockDim.x + threadIdx.x;
    int lane = threadIdx.x & 31;
    int deg = (i < n) ? g_deg[i] : 0;
    int incl = deg;
#pragma unroll
    for (int off = 1; off < 32; off <<= 1) {
        int v = __shfl_up_sync(0xffffffffu, incl, off);
        if (lane >= off) incl += v;
    }
    int excl = incl - deg;
    int base = 0;
    if (lane == 31) base = atomicAdd(&g_counter, incl);
    base = __shfl_sync(0xffffffffu, base, 31);
    if (i < n) {
        int s = base + excl;
        g_start[i] = s;
        g_fill[i]  = s;
    }
}

__global__ void fill_kernel(const int* __restrict__ src, const int* __restrict__ dst, int E) {
    int i = (blockIdx.x * blockDim.x + threadIdx.x) * 8;
    if (i + 7 < E) {
        int4 s0 = *reinterpret_cast<const int4*>(src + i);
        int4 s1 = *reinterpret_cast<const int4*>(src + i + 4);
        int4 d0 = *reinterpret_cast<const int4*>(dst + i);
        int4 d1 = *reinterpret_cast<const int4*>(dst + i + 4);
        g_col[atomicAdd(&g_fill[d0.x], 1)] = s0.x;
        g_col[atomicAdd(&g_fill[d0.y], 1)] = s0.y;
        g_col[atomicAdd(&g_fill[d0.z], 1)] = s0.z;
        g_col[atomicAdd(&g_fill[d0.w], 1)] = s0.w;
        g_col[atomicAdd(&g_fill[d1.x], 1)] = s1.x;
        g_col[atomicAdd(&g_fill[d1.y], 1)] = s1.y;
        g_col[atomicAdd(&g_fill[d1.z], 1)] = s1.z;
        g_col[atomicAdd(&g_fill[d1.w], 1)] = s1.w;
    } else {
        for (int k = i; k < E; k++)
            g_col[atomicAdd(&g_fill[dst[k]], 1)] = src[k];
    }
}

// ---------------- dense0: xl = x@W1l, xr = x@W1r + b1 (reads x once) ----------------
// Skeleton identical to R4's verified dense1_kernel; dual accumulators/stores.
__global__ void dense0_kernel(const float* __restrict__ x, const float* __restrict__ W1l,
                              const float* __restrict__ W1r, const float* __restrict__ b1,
                              float* __restrict__ xl, float* __restrict__ xr, int n) {
    __shared__ float sWl[D * D];
    __shared__ float sWr[D * D];
    __shared__ float sb[D];
    int tid = threadIdx.x;
    for (int i = tid; i < D * D; i += 256) { sWl[i] = W1l[i]; sWr[i] = W1r[i]; }
    if (tid < D) sb[tid] = b1[tid];
    __syncthreads();

    int j = tid & 31;
    int w = tid >> 5;

    for (int s = 0; s < 2; s++) {
        int i0 = blockIdx.x * 64 + w * 4 + s * 32;
        if (i0 >= n) break;
        int i1 = min(i0 + 1, n - 1);
        int i2 = min(i0 + 2, n - 1);
        int i3 = min(i0 + 3, n - 1);
        const float4* xA = reinterpret_cast<const float4*>(x + (size_t)i0 * D);
        const float4* xB = reinterpret_cast<const float4*>(x + (size_t)i1 * D);
        const float4* xC = reinterpret_cast<const float4*>(x + (size_t)i2 * D);
        const float4* xD = reinterpret_cast<const float4*>(x + (size_t)i3 * D);

        float lA0 = 0.f, lA1 = 0.f, lB0 = 0.f, lB1 = 0.f;
        float lC0 = 0.f, lC1 = 0.f, lD0 = 0.f, lD1 = 0.f;
        float rA0 = sb[j], rA1 = sb[j + 32];
        float rB0 = sb[j], rB1 = sb[j + 32];
        float rC0 = sb[j], rC1 = sb[j + 32];
        float rD0 = sb[j], rD1 = sb[j + 32];

#pragma unroll
        for (int k4 = 0; k4 < 16; k4++) {
            float4 f0 = xA[k4], f1 = xB[k4], f2v = xC[k4], f3 = xD[k4];
            int k = k4 * 4;
#pragma unroll
            for (int c = 0; c < 4; c++) {
                float wl0 = sWl[(k + c) * D + j];
                float wl1 = sWl[(k + c) * D + j + 32];
                float wr0 = sWr[(k + c) * D + j];
                float wr1 = sWr[(k + c) * D + j + 32];
                float v0 = (&f0.x)[c], v1 = (&f1.x)[c], v2 = (&f2v.x)[c], v3 = (&f3.x)[c];
                lA0 += v0 * wl0; lA1 += v0 * wl1;  rA0 += v0 * wr0; rA1 += v0 * wr1;
                lB0 += v1 * wl0; lB1 += v1 * wl1;  rB0 += v1 * wr0; rB1 += v1 * wr1;
                lC0 += v2 * wl0; lC1 += v2 * wl1;  rC0 += v2 * wr0; rC1 += v2 * wr1;
                lD0 += v3 * wl0; lD1 += v3 * wl1;  rD0 += v3 * wr0; rD1 += v3 * wr1;
            }
        }
        xl[(size_t)i0 * D + j] = lA0; xl[(size_t)i0 * D + j + 32] = lA1;
        xr[(size_t)i0 * D + j] = rA0; xr[(size_t)i0 * D + j + 32] = rA1;
        if (i0 + 1 < n) {
            xl[(size_t)i1 * D + j] = lB0; xl[(size_t)i1 * D + j + 32] = lB1;
            xr[(size_t)i1 * D + j] = rB0; xr[(size_t)i1 * D + j + 32] = rB1;
        }
        if (i0 + 2 < n) {
            xl[(size_t)i2 * D + j] = lC0; xl[(size_t)i2 * D + j + 32] = lC1;
            xr[(size_t)i2 * D + j] = rC0; xr[(size_t)i2 * D + j + 32] = rC1;
        }
        if (i0 + 3 < n) {
            xl[(size_t)i3 * D + j] = lD0; xl[(size_t)i3 * D + j + 32] = lD1;
            xr[(size_t)i3 * D + j] = rD0; xr[(size_t)i3 * D + j + 32] = rD1;
        }
    }
}

// ---------------- agg64_fused: h = relu(mean-gather(xl) + xr) ----------------
// Body identical to R4's verified agg64_kernel (unroll-4 only); fused epilogue.
__global__ void agg64_fused_kernel(const float* __restrict__ xl, const float* __restrict__ xr,
                                   float* __restrict__ h, int n) {
    int node = blockIdx.x * 8 + (threadIdx.x >> 5);
    if (node >= n) return;
    int lane = threadIdx.x & 31;

    int rs  = g_start[node];
    int deg = g_deg[node];
    const float2* f2 = reinterpret_cast<const float2*>(xl);

    float2 acc = make_float2(0.f, 0.f);
    for (int base = 0; base < deg; base += 32) {
        int m = min(32, deg - base);
        int c = (lane < m) ? __ldg(&g_col[rs + base + lane]) : 0;
        int q = 0;
        for (; q + 4 <= m; q += 4) {
            int s0 = __shfl_sync(0xffffffffu, c, q + 0);
            int s1 = __shfl_sync(0xffffffffu, c, q + 1);
            int s2 = __shfl_sync(0xffffffffu, c, q + 2);
            int s3 = __shfl_sync(0xffffffffu, c, q + 3);
            float2 v0 = __ldg(&f2[(size_t)s0 * 32 + lane]);
            float2 v1 = __ldg(&f2[(size_t)s1 * 32 + lane]);
            float2 v2 = __ldg(&f2[(size_t)s2 * 32 + lane]);
            float2 v3 = __ldg(&f2[(size_t)s3 * 32 + lane]);
            acc.x += (v0.x + v1.x) + (v2.x + v3.x);
            acc.y += (v0.y + v1.y) + (v2.y + v3.y);
        }
        for (; q < m; q++) {
            int s = __shfl_sync(0xffffffffu, c, q);
            float2 v = __ldg(&f2[(size_t)s * 32 + lane]);
            acc.x += v.x; acc.y += v.y;
        }
    }
    float inv = 1.f / fmaxf((float)deg, 1.f);
    float2 r = __ldg(&reinterpret_cast<const float2*>(xr)[(size_t)node * 32 + lane]);
    float2 hv;
    hv.x = fmaxf(acc.x * inv + r.x, 0.f);
    hv.y = fmaxf(acc.y * inv + r.y, 0.f);
    reinterpret_cast<float2*>(h)[(size_t)node * 32 + lane] = hv;
}

// ---------------- dense1b: hl = h @ W2l (verbatim from R4/passing) ----------------
__global__ void dense1b_kernel(const float* __restrict__ h, const float* __restrict__ W2l,
                               float* __restrict__ hl, int n) {
    __shared__ float sW[D * H2];
    int tid = threadIdx.x;
    for (int i = tid; i < D * H2; i += 256) sW[i] = W2l[i];
    __syncthreads();

    int j  = tid & 15;
    int il = tid >> 4;
    int base = blockIdx.x * 64;

    for (int s = 0; s < 64; s += 16) {
        int i = base + il + s;
        if (i >= n) continue;
        const float4* h4 = reinterpret_cast<const float4*>(h + (size_t)i * D);
        float acc = 0.f;
#pragma unroll
        for (int k4 = 0; k4 < 16; k4++) {
            float4 hv = h4[k4];
            int k = k4 * 4;
            acc += hv.x * sW[(k + 0) * H2 + j];
            acc += hv.y * sW[(k + 1) * H2 + j];
            acc += hv.z * sW[(k + 2) * H2 + j];
            acc += hv.w * sW[(k + 3) * H2 + j];
        }
        hl[(size_t)i * H2 + j] = acc;
    }
}

// ---------------- agg16: mean over neighbors, 16-wide (verbatim from R4) ----------------
__global__ void agg16_kernel(const float* __restrict__ feat, float* __restrict__ out, int n) {
    int node = blockIdx.x * 16 + (threadIdx.x >> 4);
    if (node >= n) return;
    int hlane = threadIdx.x & 15;

    int rs  = g_start[node];
    int deg = g_deg[node];

    float acc = 0.f;
    for (int base = 0; base < deg; base += 16) {
        int m = min(16, deg - base);
        int c = (hlane < m) ? __ldg(&g_col[rs + base + hlane]) : 0;
        int q = 0;
        for (; q + 4 <= m; q += 4) {
            int s0 = __shfl_sync(0xffffffffu, c, q + 0, 16);
            int s1 = __shfl_sync(0xffffffffu, c, q + 1, 16);
            int s2 = __shfl_sync(0xffffffffu, c, q + 2, 16);
            int s3 = __shfl_sync(0xffffffffu, c, q + 3, 16);
            float v0 = __ldg(&feat[(size_t)s0 * H2 + hlane]);
            float v1 = __ldg(&feat[(size_t)s1 * H2 + hlane]);
            float v2 = __ldg(&feat[(size_t)s2 * H2 + hlane]);
            float v3 = __ldg(&feat[(size_t)s3 * H2 + hlane]);
            acc += (v0 + v1) + (v2 + v3);
        }
        for (; q < m; q++) {
            int s = __shfl_sync(0xffffffffu, c, q, 16);
            acc += __ldg(&feat[(size_t)s * H2 + hlane]);
        }
    }
    out[(size_t)node * H2 + hlane] = acc / fmaxf((float)deg, 1.f);
}

// ---------------- dense2 + fc (verbatim from R4/passing) ----------------
__global__ void dense2_kernel(const float* __restrict__ agg2, const float* __restrict__ h,
                              const float* __restrict__ W2r, const float* __restrict__ b2,
                              const float* __restrict__ Wfc, const float* __restrict__ bfc,
                              float* __restrict__ out, int n) {
    __shared__ float sWr[D * H2];
    __shared__ float sb2[H2];
    __shared__ float sWfc[H2 * OUTW];
    __shared__ float sbfc[OUTW];
    int tid = threadIdx.x;
    for (int i = tid; i < D * H2; i += 256) sWr[i] = W2r[i];
    if (tid < H2) sb2[tid] = b2[tid];
    if (tid < H2 * OUTW) sWfc[tid] = Wfc[tid];
    if (tid < OUTW) sbfc[tid] = bfc[tid];
    __syncthreads();

    int j  = tid & 15;
    int il = tid >> 4;
    int base = blockIdx.x * 64;

    for (int s = 0; s < 64; s += 16) {
        int i = base + il + s;
        bool valid = (i < n);
        int ic = valid ? i : (n - 1);
        const float4* h4 = reinterpret_cast<const float4*>(h + (size_t)ic * D);
        float acc = sb2[j] + agg2[(size_t)ic * H2 + j];
#pragma unroll
        for (int k4 = 0; k4 < 16; k4++) {
            float4 hv = h4[k4];
            int k = k4 * 4;
            acc += hv.x * sWr[(k + 0) * H2 + j];
            acc += hv.y * sWr[(k + 1) * H2 + j];
            acc += hv.z * sWr[(k + 2) * H2 + j];
            acc += hv.w * sWr[(k + 3) * H2 + j];
        }
        float o0 = acc * sWfc[j * OUTW + 0];
        float o1 = acc * sWfc[j * OUTW + 1];
#pragma unroll
        for (int off = 8; off >= 1; off >>= 1) {
            o0 += __shfl_down_sync(0xffffffffu, o0, off, 16);
            o1 += __shfl_down_sync(0xffffffffu, o1, off, 16);
        }
        if (j == 0 && valid) {
            out[(size_t)i * OUTW + 0] = o0 + sbfc[0];
            out[(size_t)i * OUTW + 1] = o1 + sbfc[1];
        }
    }
}

// ---------------- launcher (single stream, kernels only) ----------------
extern "C" void kernel_launch(void* const* d_in, const int* in_sizes, int n_in,
                              void* d_out, int out_size) {
    const float* x   = (const float*)d_in[0];
    const int*   e   = (const int*)d_in[1];
    const float* W1l = (const float*)d_in[2];
    const float* b1  = (const float*)d_in[3];
    const float* W1r = (const float*)d_in[4];
    const float* W2l = (const float*)d_in[5];
    const float* b2  = (const float*)d_in[6];
    const float* W2r = (const float*)d_in[7];
    const float* Wfc = (const float*)d_in[8];
    const float* bfc = (const float*)d_in[9];
    float* out = (float*)d_out;

    int n = in_sizes[0] / D;
    int E = in_sizes[1] / 2;
    const int* src = e;
    const int* dst = e + E;

    float *xlp, *xrp, *hp, *hlp, *agg2p;
    cudaGetSymbolAddress((void**)&xlp, g_xl);
    cudaGetSymbolAddress((void**)&xrp, g_xr);
    cudaGetSymbolAddress((void**)&hp, g_h);
    cudaGetSymbolAddress((void**)&hlp, g_hl);
    cudaGetSymbolAddress((void**)&agg2p, g_agg2);

    // CSR build
    zero_kernel<<<(n + 255) / 256, 256>>>(n);
    hist_kernel<<<(E / 8 + 255) / 256, 256>>>(dst, E);
    alloc_kernel<<<(n + 255) / 256, 256>>>(n);
    fill_kernel<<<(E / 8 + 255) / 256, 256>>>(src, dst, E);

    // layer 1: transform both branches, then aggregate with fused epilogue
    dense0_kernel<<<(n + 63) / 64, 256>>>(x, W1l, W1r, b1, xlp, xrp, n);
    agg64_fused_kernel<<<(n + 7) / 8, 256>>>(xlp, xrp, hp, n);

    // layer 2 + fc (verbatim R4 tail)
    dense1b_kernel<<<(n + 63) / 64, 256>>>(hp, W2l, hlp, n);
    agg16_kernel<<<(n + 15) / 16, 256>>>(hlp, agg2p, n);
    dense2_kernel<<<(n + 63) / 64, 256>>>(agg2p, hp, W2r, b2, Wfc, bfc, out, n);
}

// round 8
// speedup vs baseline: 1.8510x; 1.0127x over previous
#include <cuda_runtime.h>
#include <cuda_bf16.h>
#include <cuda_fp16.h>

constexpr int MAXN = 50000;
constexpr int MAXE = 1250000;
constexpr int D    = 64;
constexpr int H2   = 16;
constexpr int OUTW = 2;

// ---------------- device scratch ----------------
__device__ int    g_deg[MAXN];
__device__ int    g_start[MAXN];
__device__ int    g_fill[MAXN];
__device__ int    g_col[MAXE];
__device__ int    g_counter;
__device__ __half g_xl[(size_t)MAXN * D];    // x @ W1l   (fp16: gathered 25x each)
__device__ float  g_xr[(size_t)MAXN * D];    // x @ W1r + b1 (fp32: read once)
__device__ float  g_h[(size_t)MAXN * D];     // layer-1 output
__device__ __half g_hl[(size_t)MAXN * H2];   // h @ W2l   (fp16: gathered 25x each)
__device__ float  g_agg2[(size_t)MAXN * H2]; // aggregated hl

// ---------------- CSR build (verbatim from passing) ----------------
__global__ void zero_kernel(int n) {
    int i = blockIdx.x * blockDim.x + threadIdx.x;
    if (i < n) g_deg[i] = 0;
    if (i == 0) g_counter = 0;
}

__global__ void hist_kernel(const int* __restrict__ dst, int E) {
    int i = (blockIdx.x * blockDim.x + threadIdx.x) * 8;
    if (i + 7 < E) {
        int4 d0 = *reinterpret_cast<const int4*>(dst + i);
        int4 d1 = *reinterpret_cast<const int4*>(dst + i + 4);
        atomicAdd(&g_deg[d0.x], 1); atomicAdd(&g_deg[d0.y], 1);
        atomicAdd(&g_deg[d0.z], 1); atomicAdd(&g_deg[d0.w], 1);
        atomicAdd(&g_deg[d1.x], 1); atomicAdd(&g_deg[d1.y], 1);
        atomicAdd(&g_deg[d1.z], 1); atomicAdd(&g_deg[d1.w], 1);
    } else {
        for (int k = i; k < E; k++) atomicAdd(&g_deg[dst[k]], 1);
    }
}

__global__ void alloc_kernel(int n) {
    int i = blockIdx.x * blockDim.x + threadIdx.x;
    int lane = threadIdx.x & 31;
    int deg = (i < n) ? g_deg[i] : 0;
    int incl = deg;
#pragma unroll
    for (int off = 1; off < 32; off <<= 1) {
        int v = __shfl_up_sync(0xffffffffu, incl, off);
        if (lane >= off) incl += v;
    }
    int excl = incl - deg;
    int base = 0;
    if (lane == 31) base = atomicAdd(&g_counter, incl);
    base = __shfl_sync(0xffffffffu, base, 31);
    if (i < n) {
        int s = base + excl;
        g_start[i] = s;
        g_fill[i]  = s;
    }
}

__global__ void fill_kernel(const int* __restrict__ src, const int* __restrict__ dst, int E) {
    int i = (blockIdx.x * blockDim.x + threadIdx.x) * 8;
    if (i + 7 < E) {
        int4 s0 = *reinterpret_cast<const int4*>(src + i);
        int4 s1 = *reinterpret_cast<const int4*>(src + i + 4);
        int4 d0 = *reinterpret_cast<const int4*>(dst + i);
        int4 d1 = *reinterpret_cast<const int4*>(dst + i + 4);
        g_col[atomicAdd(&g_fill[d0.x], 1)] = s0.x;
        g_col[atomicAdd(&g_fill[d0.y], 1)] = s0.y;
        g_col[atomicAdd(&g_fill[d0.z], 1)] = s0.z;
        g_col[atomicAdd(&g_fill[d0.w], 1)] = s0.w;
        g_col[atomicAdd(&g_fill[d1.x], 1)] = s1.x;
        g_col[atomicAdd(&g_fill[d1.y], 1)] = s1.y;
        g_col[atomicAdd(&g_fill[d1.z], 1)] = s1.z;
        g_col[atomicAdd(&g_fill[d1.w], 1)] = s1.w;
    } else {
        for (int k = i; k < E; k++)
            g_col[atomicAdd(&g_fill[dst[k]], 1)] = src[k];
    }
}

// ---------------- dense0: xl = fp16(x@W1l), xr = x@W1r + b1 ----------------
__global__ void dense0_kernel(const float* __restrict__ x, const float* __restrict__ W1l,
                              const float* __restrict__ W1r, const float* __restrict__ b1,
                              __half* __restrict__ xl, float* __restrict__ xr, int n) {
    __shared__ float sWl[D * D];
    __shared__ float sWr[D * D];
    __shared__ float sb[D];
    int tid = threadIdx.x;
    for (int i = tid; i < D * D; i += 256) { sWl[i] = W1l[i]; sWr[i] = W1r[i]; }
    if (tid < D) sb[tid] = b1[tid];
    __syncthreads();

    int j = tid & 31;
    int w = tid >> 5;

    for (int s = 0; s < 2; s++) {
        int i0 = blockIdx.x * 64 + w * 4 + s * 32;
        if (i0 >= n) break;
        int i1 = min(i0 + 1, n - 1);
        int i2 = min(i0 + 2, n - 1);
        int i3 = min(i0 + 3, n - 1);
        const float4* xA = reinterpret_cast<const float4*>(x + (size_t)i0 * D);
        const float4* xB = reinterpret_cast<const float4*>(x + (size_t)i1 * D);
        const float4* xC = reinterpret_cast<const float4*>(x + (size_t)i2 * D);
        const float4* xD = reinterpret_cast<const float4*>(x + (size_t)i3 * D);

        float lA0 = 0.f, lA1 = 0.f, lB0 = 0.f, lB1 = 0.f;
        float lC0 = 0.f, lC1 = 0.f, lD0 = 0.f, lD1 = 0.f;
        float rA0 = sb[j], rA1 = sb[j + 32];
        float rB0 = sb[j], rB1 = sb[j + 32];
        float rC0 = sb[j], rC1 = sb[j + 32];
        float rD0 = sb[j], rD1 = sb[j + 32];

#pragma unroll
        for (int k4 = 0; k4 < 16; k4++) {
            float4 f0 = xA[k4], f1 = xB[k4], f2v = xC[k4], f3 = xD[k4];
            int k = k4 * 4;
#pragma unroll
            for (int c = 0; c < 4; c++) {
                float wl0 = sWl[(k + c) * D + j];
                float wl1 = sWl[(k + c) * D + j + 32];
                float wr0 = sWr[(k + c) * D + j];
                float wr1 = sWr[(k + c) * D + j + 32];
                float v0 = (&f0.x)[c], v1 = (&f1.x)[c], v2 = (&f2v.x)[c], v3 = (&f3.x)[c];
                lA0 += v0 * wl0; lA1 += v0 * wl1;  rA0 += v0 * wr0; rA1 += v0 * wr1;
                lB0 += v1 * wl0; lB1 += v1 * wl1;  rB0 += v1 * wr0; rB1 += v1 * wr1;
                lC0 += v2 * wl0; lC1 += v2 * wl1;  rC0 += v2 * wr0; rC1 += v2 * wr1;
                lD0 += v3 * wl0; lD1 += v3 * wl1;  rD0 += v3 * wr0; rD1 += v3 * wr1;
            }
        }
        xl[(size_t)i0 * D + j] = __float2half_rn(lA0);
        xl[(size_t)i0 * D + j + 32] = __float2half_rn(lA1);
        xr[(size_t)i0 * D + j] = rA0; xr[(size_t)i0 * D + j + 32] = rA1;
        if (i0 + 1 < n) {
            xl[(size_t)i1 * D + j] = __float2half_rn(lB0);
            xl[(size_t)i1 * D + j + 32] = __float2half_rn(lB1);
            xr[(size_t)i1 * D + j] = rB0; xr[(size_t)i1 * D + j + 32] = rB1;
        }
        if (i0 + 2 < n) {
            xl[(size_t)i2 * D + j] = __float2half_rn(lC0);
            xl[(size_t)i2 * D + j + 32] = __float2half_rn(lC1);
            xr[(size_t)i2 * D + j] = rC0; xr[(size_t)i2 * D + j + 32] = rC1;
        }
        if (i0 + 3 < n) {
            xl[(size_t)i3 * D + j] = __float2half_rn(lD0);
            xl[(size_t)i3 * D + j + 32] = __float2half_rn(lD1);
            xr[(size_t)i3 * D + j] = rD0; xr[(size_t)i3 * D + j + 32] = rD1;
        }
    }
}

// ---------------- agg64_fused: h = relu(mean-gather(fp16 xl) + xr) ----------------
// Same verified skeleton; lane loads __half2 (row = 128B/edge, one L2 line).
__global__ void agg64_fused_kernel(const __half* __restrict__ xl, const float* __restrict__ xr,
                                   float* __restrict__ h, int n) {
    int node = blockIdx.x * 8 + (threadIdx.x >> 5);
    if (node >= n) return;
    int lane = threadIdx.x & 31;

    int rs  = g_start[node];
    int deg = g_deg[node];
    const __half2* f2 = reinterpret_cast<const __half2*>(xl);

    float2 acc = make_float2(0.f, 0.f);
    for (int base = 0; base < deg; base += 32) {
        int m = min(32, deg - base);
        int c = (lane < m) ? __ldg(&g_col[rs + base + lane]) : 0;
        int q = 0;
        for (; q + 4 <= m; q += 4) {
            int s0 = __shfl_sync(0xffffffffu, c, q + 0);
            int s1 = __shfl_sync(0xffffffffu, c, q + 1);
            int s2 = __shfl_sync(0xffffffffu, c, q + 2);
            int s3 = __shfl_sync(0xffffffffu, c, q + 3);
            float2 v0 = __half22float2(__ldg(&f2[(size_t)s0 * 32 + lane]));
            float2 v1 = __half22float2(__ldg(&f2[(size_t)s1 * 32 + lane]));
            float2 v2 = __half22float2(__ldg(&f2[(size_t)s2 * 32 + lane]));
            float2 v3 = __half22float2(__ldg(&f2[(size_t)s3 * 32 + lane]));
            acc.x += (v0.x + v1.x) + (v2.x + v3.x);
            acc.y += (v0.y + v1.y) + (v2.y + v3.y);
        }
        for (; q < m; q++) {
            int s = __shfl_sync(0xffffffffu, c, q);
            float2 v = __half22float2(__ldg(&f2[(size_t)s * 32 + lane]));
            acc.x += v.x; acc.y += v.y;
        }
    }
    float inv = 1.f / fmaxf((float)deg, 1.f);
    // lane covers features (2*lane, 2*lane+1)
    const float2* xr2 = reinterpret_cast<const float2*>(xr);
    float2 r = __ldg(&xr2[(size_t)node * 32 + lane]);
    float2 hv;
    hv.x = fmaxf(acc.x * inv + r.x, 0.f);
    hv.y = fmaxf(acc.y * inv + r.y, 0.f);
    reinterpret_cast<float2*>(h)[(size_t)node * 32 + lane] = hv;
}

// ---------------- dense1b: hl = fp16(h @ W2l) ----------------
__global__ void dense1b_kernel(const float* __restrict__ h, const float* __restrict__ W2l,
                               __half* __restrict__ hl, int n) {
    __shared__ float sW[D * H2];
    int tid = threadIdx.x;
    for (int i = tid; i < D * H2; i += 256) sW[i] = W2l[i];
    __syncthreads();

    int j  = tid & 15;
    int il = tid >> 4;
    int base = blockIdx.x * 64;

    for (int s = 0; s < 64; s += 16) {
        int i = base + il + s;
        if (i >= n) continue;
        const float4* h4 = reinterpret_cast<const float4*>(h + (size_t)i * D);
        float acc = 0.f;
#pragma unroll
        for (int k4 = 0; k4 < 16; k4++) {
            float4 hv = h4[k4];
            int k = k4 * 4;
            acc += hv.x * sW[(k + 0) * H2 + j];
            acc += hv.y * sW[(k + 1) * H2 + j];
            acc += hv.z * sW[(k + 2) * H2 + j];
            acc += hv.w * sW[(k + 3) * H2 + j];
        }
        hl[(size_t)i * H2 + j] = __float2half_rn(acc);
    }
}

// ---------------- agg16: mean over neighbors of fp16 hl ----------------
__global__ void agg16_kernel(const __half* __restrict__ feat, float* __restrict__ out, int n) {
    int node = blockIdx.x * 16 + (threadIdx.x >> 4);
    if (node >= n) return;
    int hlane = threadIdx.x & 15;

    int rs  = g_start[node];
    int deg = g_deg[node];

    float acc = 0.f;
    for (int base = 0; base < deg; base += 16) {
        int m = min(16, deg - base);
        int c = (hlane < m) ? __ldg(&g_col[rs + base + hlane]) : 0;
        int q = 0;
        for (; q + 4 <= m; q += 4) {
            int s0 = __shfl_sync(0xffffffffu, c, q + 0, 16);
            int s1 = __shfl_sync(0xffffffffu, c, q + 1, 16);
            int s2 = __shfl_sync(0xffffffffu, c, q + 2, 16);
            int s3 = __shfl_sync(0xffffffffu, c, q + 3, 16);
            float v0 = __half2float(__ldg(&feat[(size_t)s0 * H2 + hlane]));
            float v1 = __half2float(__ldg(&feat[(size_t)s1 * H2 + hlane]));
            float v2 = __half2float(__ldg(&feat[(size_t)s2 * H2 + hlane]));
            float v3 = __half2float(__ldg(&feat[(size_t)s3 * H2 + hlane]));
            acc += (v0 + v1) + (v2 + v3);
        }
        for (; q < m; q++) {
            int s = __shfl_sync(0xffffffffu, c, q, 16);
            acc += __half2float(__ldg(&feat[(size_t)s * H2 + hlane]));
        }
    }
    out[(size_t)node * H2 + hlane] = acc / fmaxf((float)deg, 1.f);
}

// ---------------- dense2 + fc (verbatim from passing) ----------------
__global__ void dense2_kernel(const float* __restrict__ agg2, const float* __restrict__ h,
                              const float* __restrict__ W2r, const float* __restrict__ b2,
                              const float* __restrict__ Wfc, const float* __restrict__ bfc,
                              float* __restrict__ out, int n) {
    __shared__ float sWr[D * H2];
    __shared__ float sb2[H2];
    __shared__ float sWfc[H2 * OUTW];
    __shared__ float sbfc[OUTW];
    int tid = threadIdx.x;
    for (int i = tid; i < D * H2; i += 256) sWr[i] = W2r[i];
    if (tid < H2) sb2[tid] = b2[tid];
    if (tid < H2 * OUTW) sWfc[tid] = Wfc[tid];
    if (tid < OUTW) sbfc[tid] = bfc[tid];
    __syncthreads();

    int j  = tid & 15;
    int il = tid >> 4;
    int base = blockIdx.x * 64;

    for (int s = 0; s < 64; s += 16) {
        int i = base + il + s;
        bool valid = (i < n);
        int ic = valid ? i : (n - 1);
        const float4* h4 = reinterpret_cast<const float4*>(h + (size_t)ic * D);
        float acc = sb2[j] + agg2[(size_t)ic * H2 + j];
#pragma unroll
        for (int k4 = 0; k4 < 16; k4++) {
            float4 hv = h4[k4];
            int k = k4 * 4;
            acc += hv.x * sWr[(k + 0) * H2 + j];
            acc += hv.y * sWr[(k + 1) * H2 + j];
            acc += hv.z * sWr[(k + 2) * H2 + j];
            acc += hv.w * sWr[(k + 3) * H2 + j];
        }
        float o0 = acc * sWfc[j * OUTW + 0];
        float o1 = acc * sWfc[j * OUTW + 1];
#pragma unroll
        for (int off = 8; off >= 1; off >>= 1) {
            o0 += __shfl_down_sync(0xffffffffu, o0, off, 16);
            o1 += __shfl_down_sync(0xffffffffu, o1, off, 16);
        }
        if (j == 0 && valid) {
            out[(size_t)i * OUTW + 0] = o0 + sbfc[0];
            out[(size_t)i * OUTW + 1] = o1 + sbfc[1];
        }
    }
}

// ---------------- launcher (single stream, kernels only) ----------------
extern "C" void kernel_launch(void* const* d_in, const int* in_sizes, int n_in,
                              void* d_out, int out_size) {
    const float* x   = (const float*)d_in[0];
    const int*   e   = (const int*)d_in[1];
    const float* W1l = (const float*)d_in[2];
    const float* b1  = (const float*)d_in[3];
    const float* W1r = (const float*)d_in[4];
    const float* W2l = (const float*)d_in[5];
    const float* b2  = (const float*)d_in[6];
    const float* W2r = (const float*)d_in[7];
    const float* Wfc = (const float*)d_in[8];
    const float* bfc = (const float*)d_in[9];
    float* out = (float*)d_out;

    int n = in_sizes[0] / D;
    int E = in_sizes[1] / 2;
    const int* src = e;
    const int* dst = e + E;

    __half *xlp, *hlp;
    float *xrp, *hp, *agg2p;
    cudaGetSymbolAddress((void**)&xlp, g_xl);
    cudaGetSymbolAddress((void**)&xrp, g_xr);
    cudaGetSymbolAddress((void**)&hp, g_h);
    cudaGetSymbolAddress((void**)&hlp, g_hl);
    cudaGetSymbolAddress((void**)&agg2p, g_agg2);

    // CSR build
    zero_kernel<<<(n + 255) / 256, 256>>>(n);
    hist_kernel<<<(E / 8 + 255) / 256, 256>>>(dst, E);
    alloc_kernel<<<(n + 255) / 256, 256>>>(n);
    fill_kernel<<<(E / 8 + 255) / 256, 256>>>(src, dst, E);

    // layer 1: transform both branches, then aggregate (fp16 gather)
    dense0_kernel<<<(n + 63) / 64, 256>>>(x, W1l, W1r, b1, xlp, xrp, n);
    agg64_fused_kernel<<<(n + 7) / 8, 256>>>(xlp, xrp, hp, n);

    // layer 2 + fc
    dense1b_kernel<<<(n + 63) / 64, 256>>>(hp, W2l, hlp, n);
    agg16_kernel<<<(n + 15) / 16, 256>>>(hlp, agg2p, n);
    dense2_kernel<<<(n + 63) / 64, 256>>>(agg2p, hp, W2r, b2, Wfc, bfc, out, n);
}